// round 6
// baseline (speedup 1.0000x reference)
#include <cuda_runtime.h>
#include <cuda_fp16.h>
#include <cstdint>

// ---------------- problem constants ----------------
#define D_M   8192      // B*S
#define D_K   4096
#define D_N   11008

#define BM    128
#define BN    256
#define BK    64        // 64 fp16 = 128B rows (SW128 atom)
#define KITERS (D_K / BK)   // 64
#define NS    4             // pipeline stages

static constexpr int MT = D_M / BM;   // 64
static constexpr int NT = D_N / BN;   // 43

static constexpr int A_TILE_BYTES = BM * BK * 2;  // 16384
static constexpr int B_TILE_BYTES = BN * BK * 2;  // 32768

static constexpr int NTHREADS = 256;  // 8 warps: 2(M) x 4(N), warp tile 64x64

// smem layout (~194 KB -> 1 CTA/SM)
static constexpr int SM_FULL  = 0;                    // NS * 8
static constexpr int SM_EMPTY = SM_FULL + NS * 8;     // 32
static constexpr int SM_BIAS  = 128;                  // BN floats = 1024B
static constexpr int SM_A     = 2048;                              // 1024-aligned
static constexpr int SM_B     = SM_A + NS * A_TILE_BYTES;          // 67584
static constexpr int SMEM_TOTAL = SM_B + NS * B_TILE_BYTES;        // 198656

// ---------------- scratch (tiled, pre-swizzled fp16) ----------------
__device__ __align__(1024) __half g_xt[(size_t)D_M * D_K];   // 64 MiB
__device__ __align__(1024) __half g_wt[(size_t)D_N * D_K];   // 86 MiB

// ---------------- PTX helpers ----------------
__device__ __forceinline__ uint32_t smem_u32(const void* p) {
    uint32_t a;
    asm("{ .reg .u64 t; cvta.to.shared.u64 t, %1; cvt.u32.u64 %0, t; }" : "=r"(a) : "l"(p));
    return a;
}
__device__ __forceinline__ uint32_t elect_one() {
    uint32_t p;
    asm volatile("{ .reg .pred p; elect.sync _|p, 0xFFFFFFFF; selp.b32 %0, 1, 0, p; }" : "=r"(p));
    return p;
}
#define MBAR_INIT(a, cnt) \
    asm volatile("mbarrier.init.shared.b64 [%0], %1;" :: "r"(a), "r"((uint32_t)(cnt)) : "memory")
#define MBAR_EXPECT_TX(a, b) \
    asm volatile("mbarrier.arrive.expect_tx.shared.b64 _, [%0], %1;" :: "r"(a), "r"((uint32_t)(b)) : "memory")
#define MBAR_ARRIVE(a) \
    asm volatile("mbarrier.arrive.shared.b64 _, [%0];" :: "r"(a) : "memory")

#define MBAR_WAIT(a, ph) do {                                                   \
    uint32_t _m = (a); uint32_t _p = (uint32_t)(ph); uint32_t _d;               \
    asm volatile("{ .reg .pred p; mbarrier.try_wait.parity.acquire.cta.shared::cta.b64 p, [%1], %2; selp.b32 %0,1,0,p; }" \
        : "=r"(_d) : "r"(_m), "r"(_p) : "memory");                              \
    if (!_d) { asm volatile("{ .reg .pred P1; WL%=:\n\t"                        \
        "mbarrier.try_wait.parity.acquire.cta.shared::cta.b64 P1, [%0], %1, 0x989680;\n\t" \
        "@P1 bra.uni WD%=;\n\t bra.uni WL%=;\n\t WD%=: }"                       \
        :: "r"(_m), "r"(_p) : "memory"); }                                      \
} while (0)

__device__ __forceinline__ void bulk_g2s(uint32_t dst, const void* src, uint32_t bytes, uint32_t mbar) {
    asm volatile("cp.async.bulk.shared::cta.global.mbarrier::complete_tx::bytes [%0], [%1], %2, [%3];"
        :: "r"(dst), "l"(src), "r"(bytes), "r"(mbar) : "memory");
}

__device__ __forceinline__ void ldmx4(uint32_t& r0, uint32_t& r1, uint32_t& r2, uint32_t& r3, uint32_t a) {
    asm volatile("ldmatrix.sync.aligned.m8n8.x4.shared.b16 {%0,%1,%2,%3}, [%4];"
        : "=r"(r0), "=r"(r1), "=r"(r2), "=r"(r3) : "r"(a));
}

__device__ __forceinline__ void mma16816(float* c, const uint32_t* a, uint32_t b0, uint32_t b1) {
    asm volatile("mma.sync.aligned.m16n8k16.row.col.f32.f16.f16.f32 "
        "{%0,%1,%2,%3}, {%4,%5,%6,%7}, {%8,%9}, {%0,%1,%2,%3};"
        : "+f"(c[0]), "+f"(c[1]), "+f"(c[2]), "+f"(c[3])
        : "r"(a[0]), "r"(a[1]), "r"(a[2]), "r"(a[3]), "r"(b0), "r"(b1));
}

__device__ __forceinline__ uint32_t swz(uint32_t off) { return off ^ ((off >> 3) & 0x70); }

// ---------------- fused converter kernel (pre-swizzled fp16 tiles) ----------------
__global__ void conv_kernel(const float* __restrict__ x, const int* __restrict__ qw,
                            const float* __restrict__ zp_p,
                            __half* __restrict__ xt, __half* __restrict__ wt) {
    int b = blockIdx.x;
    if (b < MT * KITERS) {
        int mt = b / KITERS, kc = b % KITERS;
        const float* src = x + (size_t)mt * BM * D_K + (size_t)kc * BK;
        char* dst = (char*)(xt + (size_t)b * (BM * BK));
        for (int i = threadIdx.x; i < BM * BK / 2; i += blockDim.x) {
            int row = i >> 5, c2 = i & 31;
            float2 v = *(const float2*)(src + (size_t)row * D_K + c2 * 2);
            __half2 h = __floats2half2_rn(v.x, v.y);
            *(__half2*)(dst + swz(row * 128 + c2 * 4)) = h;
        }
    } else {
        int t = b - MT * KITERS;
        float zp = *zp_p;
        int nt = t / KITERS, kc = t % KITERS;
        const int* src = qw + (size_t)nt * BN * D_K + (size_t)kc * BK;
        char* dst = (char*)(wt + (size_t)t * (BN * BK));
        for (int i = threadIdx.x; i < BN * BK / 2; i += blockDim.x) {
            int row = i >> 5, c2 = i & 31;
            int2 q = *(const int2*)(src + (size_t)row * D_K + c2 * 2);
            __half2 h = __floats2half2_rn((float)q.x - zp, (float)q.y - zp);
            *(__half2*)(dst + swz(row * 128 + c2 * 4)) = h;
        }
    }
}

// ---------------- main GEMM kernel ----------------
// 256 threads, 8 warps in 2(M) x 4(N); warp tile 64 x 64 (128 f32 acc regs).
__global__ void __launch_bounds__(NTHREADS, 1)
gemm_kernel(const float* __restrict__ scale_p, const float* __restrict__ bias,
            float* __restrict__ out) {
    extern __shared__ char smem[];
    uint32_t sb = smem_u32(smem);
    int tid = threadIdx.x, wid = tid >> 5, lane = tid & 31;
    int wm = wid & 1;          // 0..1  (M)
    int wn = wid >> 1;         // 0..3  (N)

    // tile decode with M-group swizzle for L2 reuse
    const int GROUP = 16;
    int bid = blockIdx.x;
    int tpg = GROUP * NT;
    int g = bid / tpg, r = bid % tpg;
    int mt = g * GROUP + (r % GROUP);
    int nt = r / GROUP;

    if (tid == 0) {
        for (int s = 0; s < NS; s++) {
            MBAR_INIT(sb + SM_FULL  + s * 8, 1);
            MBAR_INIT(sb + SM_EMPTY + s * 8, 8);
        }
    }
    for (int i = tid; i < BN; i += NTHREADS)
        ((float*)(smem + SM_BIAS))[i] = bias[(size_t)nt * BN + i];
    __syncthreads();

    const char* asrc = (const char*)g_xt + (size_t)mt * KITERS * A_TILE_BYTES;
    const char* bsrc = (const char*)g_wt + (size_t)nt * KITERS * B_TILE_BYTES;

    // prologue: fill all NS stages
    if (tid == 0) {
        for (int s = 0; s < NS; s++) {
            MBAR_EXPECT_TX(sb + SM_FULL + s * 8, A_TILE_BYTES + B_TILE_BYTES);
            bulk_g2s(sb + SM_A + s * A_TILE_BYTES, asrc + (size_t)s * A_TILE_BYTES,
                     A_TILE_BYTES, sb + SM_FULL + s * 8);
            bulk_g2s(sb + SM_B + s * B_TILE_BYTES, bsrc + (size_t)s * B_TILE_BYTES,
                     B_TILE_BYTES, sb + SM_FULL + s * 8);
        }
    }

    // per-lane ldmatrix addressing: hoisted swizzled bases.
    // Pre-swizzle offsets have bits 5-6 == 0 (lcb is bit 4 only), so
    // swz(off + kk*32) == swz(off) XOR (kk*32).  (XOR — the swizzle XOR can
    // set bits 5-6; an ADD there would carry into bit 7.)
    int lrow = (lane & 7) + ((lane >> 3) & 1) * 8;   // 0..15 within 16-row block
    int lcb  = (lane >> 4) * 16;                     // 0 or 16 bytes (k half)
    uint32_t aoff[4], boff[4];
    #pragma unroll
    for (int mi = 0; mi < 4; mi++)
        aoff[mi] = swz((uint32_t)(wm * 64 + mi * 16 + lrow) * 128 + lcb);
    #pragma unroll
    for (int gg = 0; gg < 4; gg++)
        boff[gg] = swz((uint32_t)(wn * 64 + gg * 16 + lrow) * 128 + lcb);

    float acc[4][4][2][4];    // [mi][gg][sub][4] = 128 f32
    #pragma unroll
    for (int i = 0; i < 4; i++)
        #pragma unroll
        for (int j = 0; j < 4; j++)
            #pragma unroll
            for (int k = 0; k < 2; k++)
                #pragma unroll
                for (int l = 0; l < 4; l++) acc[i][j][k][l] = 0.f;

    for (int it = 0; it < KITERS; ++it) {
        int s = it & (NS - 1);
        int ph = (it >> 2) & 1;   // NS == 4
        MBAR_WAIT(sb + SM_FULL + s * 8, ph);

        uint32_t abase = sb + SM_A + s * A_TILE_BYTES;
        uint32_t bbase = sb + SM_B + s * B_TILE_BYTES;

        #pragma unroll
        for (int kk = 0; kk < 4; kk++) {           // four k16 steps in BK=64
            uint32_t kx = (uint32_t)(kk << 5);     // XOR-combine with swizzled base
            uint32_t afr[4][4];
            #pragma unroll
            for (int mi = 0; mi < 4; mi++)
                ldmx4(afr[mi][0], afr[mi][1], afr[mi][2], afr[mi][3],
                      abase + (aoff[mi] ^ kx));
            uint32_t bfr[4][4];
            #pragma unroll
            for (int gg = 0; gg < 4; gg++)
                ldmx4(bfr[gg][0], bfr[gg][1], bfr[gg][2], bfr[gg][3],
                      bbase + (boff[gg] ^ kx));
            #pragma unroll
            for (int mi = 0; mi < 4; mi++)
                #pragma unroll
                for (int gg = 0; gg < 4; gg++) {
                    mma16816(acc[mi][gg][0], afr[mi], bfr[gg][0], bfr[gg][2]);
                    mma16816(acc[mi][gg][1], afr[mi], bfr[gg][1], bfr[gg][3]);
                }
        }

        if (elect_one()) MBAR_ARRIVE(sb + SM_EMPTY + s * 8);

        // refill this slot for iteration it+NS (same parity as our arrive above)
        if (tid == 0 && it + NS < KITERS) {
            MBAR_WAIT(sb + SM_EMPTY + s * 8, ph);
            int nx = it + NS;
            MBAR_EXPECT_TX(sb + SM_FULL + s * 8, A_TILE_BYTES + B_TILE_BYTES);
            bulk_g2s(sb + SM_A + s * A_TILE_BYTES, asrc + (size_t)nx * A_TILE_BYTES,
                     A_TILE_BYTES, sb + SM_FULL + s * 8);
            bulk_g2s(sb + SM_B + s * B_TILE_BYTES, bsrc + (size_t)nx * B_TILE_BYTES,
                     B_TILE_BYTES, sb + SM_FULL + s * 8);
        }
    }

    // ---- epilogue ----
    float scl = *scale_p;
    const float* bs = (const float*)(smem + SM_BIAS);
    int qrow = lane >> 2;          // 0..7
    int qcol = (lane & 3) * 2;     // 0,2,4,6
    #pragma unroll
    for (int mi = 0; mi < 4; mi++) {
        #pragma unroll
        for (int gg = 0; gg < 4; gg++) {
            #pragma unroll
            for (int sub = 0; sub < 2; sub++) {
                int ncol = wn * 64 + gg * 16 + sub * 8 + qcol;       // local in BN
                int m0   = mt * BM + wm * 64 + mi * 16 + qrow;
                size_t og = (size_t)m0 * D_N + (size_t)nt * BN + ncol;
                float b0 = bs[ncol], b1 = bs[ncol + 1];
                float2 v0, v1;
                v0.x = fmaf(scl, acc[mi][gg][sub][0], b0);
                v0.y = fmaf(scl, acc[mi][gg][sub][1], b1);
                v1.x = fmaf(scl, acc[mi][gg][sub][2], b0);
                v1.y = fmaf(scl, acc[mi][gg][sub][3], b1);
                *(float2*)(out + og) = v0;
                *(float2*)(out + og + (size_t)8 * D_N) = v1;
            }
        }
    }
}

// ---------------- launch ----------------
extern "C" void kernel_launch(void* const* d_in, const int* in_sizes, int n_in,
                              void* d_out, int out_size) {
    const float* x     = (const float*)d_in[0];
    const int*   qw    = (const int*)d_in[1];
    const float* scale = (const float*)d_in[2];
    const float* zp    = (const float*)d_in[3];
    const float* bias  = (const float*)d_in[4];
    float* out = (float*)d_out;

    __half* xt; cudaGetSymbolAddress((void**)&xt, g_xt);
    __half* wt; cudaGetSymbolAddress((void**)&wt, g_wt);

    cudaFuncSetAttribute(gemm_kernel, cudaFuncAttributeMaxDynamicSharedMemorySize, SMEM_TOTAL);

    conv_kernel<<<MT * KITERS + NT * KITERS, 256>>>(x, qw, zp, xt, wt);
    gemm_kernel<<<MT * NT, NTHREADS, SMEM_TOTAL>>>(scale, bias, out);
}

// round 7
// speedup vs baseline: 1.0262x; 1.0262x over previous
#include <cuda_runtime.h>
#include <cuda_fp16.h>
#include <cstdint>

// ---------------- problem constants ----------------
#define D_M   8192      // B*S
#define D_K   4096
#define D_N   11008

#define BM    128
#define BN    128
#define BK    64        // 64 fp16 = 128B rows (SW128 atom)
#define KITERS (D_K / BK)   // 64
#define NS    3             // pipeline stages (explicit cursor)

static constexpr int MT = D_M / BM;   // 64
static constexpr int NT = D_N / BN;   // 86

static constexpr int A_TILE_BYTES = BM * BK * 2;  // 16384
static constexpr int B_TILE_BYTES = BN * BK * 2;  // 16384

static constexpr int NTHREADS = 128;  // 4 warps: 2(M) x 2(N), warp tile 64x64

// smem layout (per CTA ~97 KB -> 2 CTAs/SM)
static constexpr int SM_FULL  = 0;                    // NS * 8
static constexpr int SM_EMPTY = SM_FULL + NS * 8;     // 24
static constexpr int SM_BIAS  = 128;                  // BN floats = 512B
static constexpr int SM_A     = 1024;                              // 1024-aligned
static constexpr int SM_B     = SM_A + NS * A_TILE_BYTES;          // 50176
static constexpr int SMEM_TOTAL = SM_B + NS * B_TILE_BYTES;        // 99328

// ---------------- scratch (tiled, pre-swizzled fp16) ----------------
__device__ __align__(1024) __half g_xt[(size_t)D_M * D_K];   // 64 MiB
__device__ __align__(1024) __half g_wt[(size_t)D_N * D_K];   // 86 MiB

// ---------------- PTX helpers ----------------
__device__ __forceinline__ uint32_t smem_u32(const void* p) {
    uint32_t a;
    asm("{ .reg .u64 t; cvta.to.shared.u64 t, %1; cvt.u32.u64 %0, t; }" : "=r"(a) : "l"(p));
    return a;
}
__device__ __forceinline__ uint32_t elect_one() {
    uint32_t p;
    asm volatile("{ .reg .pred p; elect.sync _|p, 0xFFFFFFFF; selp.b32 %0, 1, 0, p; }" : "=r"(p));
    return p;
}
#define MBAR_INIT(a, cnt) \
    asm volatile("mbarrier.init.shared.b64 [%0], %1;" :: "r"(a), "r"((uint32_t)(cnt)) : "memory")
#define MBAR_EXPECT_TX(a, b) \
    asm volatile("mbarrier.arrive.expect_tx.shared.b64 _, [%0], %1;" :: "r"(a), "r"((uint32_t)(b)) : "memory")
#define MBAR_ARRIVE(a) \
    asm volatile("mbarrier.arrive.shared.b64 _, [%0];" :: "r"(a) : "memory")

#define MBAR_WAIT(a, ph) do {                                                   \
    uint32_t _m = (a); uint32_t _p = (uint32_t)(ph); uint32_t _d;               \
    asm volatile("{ .reg .pred p; mbarrier.try_wait.parity.acquire.cta.shared::cta.b64 p, [%1], %2; selp.b32 %0,1,0,p; }" \
        : "=r"(_d) : "r"(_m), "r"(_p) : "memory");                              \
    if (!_d) { asm volatile("{ .reg .pred P1; WL%=:\n\t"                        \
        "mbarrier.try_wait.parity.acquire.cta.shared::cta.b64 P1, [%0], %1, 0x989680;\n\t" \
        "@P1 bra.uni WD%=;\n\t bra.uni WL%=;\n\t WD%=: }"                       \
        :: "r"(_m), "r"(_p) : "memory"); }                                      \
} while (0)

__device__ __forceinline__ void bulk_g2s(uint32_t dst, const void* src, uint32_t bytes, uint32_t mbar) {
    asm volatile("cp.async.bulk.shared::cta.global.mbarrier::complete_tx::bytes [%0], [%1], %2, [%3];"
        :: "r"(dst), "l"(src), "r"(bytes), "r"(mbar) : "memory");
}

__device__ __forceinline__ void ldmx4(uint32_t& r0, uint32_t& r1, uint32_t& r2, uint32_t& r3, uint32_t a) {
    asm volatile("ldmatrix.sync.aligned.m8n8.x4.shared.b16 {%0,%1,%2,%3}, [%4];"
        : "=r"(r0), "=r"(r1), "=r"(r2), "=r"(r3) : "r"(a));
}

__device__ __forceinline__ void mma16816(float* c, const uint32_t* a, uint32_t b0, uint32_t b1) {
    asm volatile("mma.sync.aligned.m16n8k16.row.col.f32.f16.f16.f32 "
        "{%0,%1,%2,%3}, {%4,%5,%6,%7}, {%8,%9}, {%0,%1,%2,%3};"
        : "+f"(c[0]), "+f"(c[1]), "+f"(c[2]), "+f"(c[3])
        : "r"(a[0]), "r"(a[1]), "r"(a[2]), "r"(a[3]), "r"(b0), "r"(b1));
}

__device__ __forceinline__ uint32_t swz(uint32_t off) { return off ^ ((off >> 3) & 0x70); }

// ---------------- fused converter kernel (pre-swizzled fp16 tiles) ----------------
__global__ void conv_kernel(const float* __restrict__ x, const int* __restrict__ qw,
                            const float* __restrict__ zp_p,
                            __half* __restrict__ xt, __half* __restrict__ wt) {
    int b = blockIdx.x;
    if (b < MT * KITERS) {
        int mt = b / KITERS, kc = b % KITERS;
        const float* src = x + (size_t)mt * BM * D_K + (size_t)kc * BK;
        char* dst = (char*)(xt + (size_t)b * (BM * BK));
        for (int i = threadIdx.x; i < BM * BK / 2; i += blockDim.x) {
            int row = i >> 5, c2 = i & 31;
            float2 v = *(const float2*)(src + (size_t)row * D_K + c2 * 2);
            __half2 h = __floats2half2_rn(v.x, v.y);
            *(__half2*)(dst + swz(row * 128 + c2 * 4)) = h;
        }
    } else {
        int t = b - MT * KITERS;
        float zp = *zp_p;
        int nt = t / KITERS, kc = t % KITERS;
        const int* src = qw + (size_t)nt * BN * D_K + (size_t)kc * BK;
        char* dst = (char*)(wt + (size_t)t * (BN * BK));
        for (int i = threadIdx.x; i < BN * BK / 2; i += blockDim.x) {
            int row = i >> 5, c2 = i & 31;
            int2 q = *(const int2*)(src + (size_t)row * D_K + c2 * 2);
            __half2 h = __floats2half2_rn((float)q.x - zp, (float)q.y - zp);
            *(__half2*)(dst + swz(row * 128 + c2 * 4)) = h;
        }
    }
}

// ---------------- main GEMM kernel ----------------
// 128 threads, 4 warps in 2(M) x 2(N); warp tile 64 x 64 (128 f32 acc regs).
// 2 CTAs / SM; fragments double-buffered across kk (explicit LDSM prefetch).
__global__ void __launch_bounds__(NTHREADS, 2)
gemm_kernel(const float* __restrict__ scale_p, const float* __restrict__ bias,
            float* __restrict__ out) {
    extern __shared__ char smem[];
    uint32_t sb = smem_u32(smem);
    int tid = threadIdx.x, wid = tid >> 5, lane = tid & 31;
    int wm = wid & 1;          // 0..1  (M)
    int wn = wid >> 1;         // 0..1  (N)

    // tile decode with M-group swizzle for L2 reuse
    const int GROUP = 16;
    int bid = blockIdx.x;
    int tpg = GROUP * NT;
    int g = bid / tpg, r = bid % tpg;
    int mt = g * GROUP + (r % GROUP);
    int nt = r / GROUP;

    if (tid == 0) {
        for (int s = 0; s < NS; s++) {
            MBAR_INIT(sb + SM_FULL  + s * 8, 1);
            MBAR_INIT(sb + SM_EMPTY + s * 8, 4);
        }
    }
    for (int i = tid; i < BN; i += NTHREADS)
        ((float*)(smem + SM_BIAS))[i] = bias[(size_t)nt * BN + i];
    __syncthreads();

    const char* asrc = (const char*)g_xt + (size_t)mt * KITERS * A_TILE_BYTES;
    const char* bsrc = (const char*)g_wt + (size_t)nt * KITERS * B_TILE_BYTES;

    // prologue: fill all NS stages
    if (tid == 0) {
        for (int s = 0; s < NS; s++) {
            MBAR_EXPECT_TX(sb + SM_FULL + s * 8, A_TILE_BYTES + B_TILE_BYTES);
            bulk_g2s(sb + SM_A + s * A_TILE_BYTES, asrc + (size_t)s * A_TILE_BYTES,
                     A_TILE_BYTES, sb + SM_FULL + s * 8);
            bulk_g2s(sb + SM_B + s * B_TILE_BYTES, bsrc + (size_t)s * B_TILE_BYTES,
                     B_TILE_BYTES, sb + SM_FULL + s * 8);
        }
    }

    // per-lane ldmatrix addressing: hoisted swizzled bases.
    // Pre-swizzle offsets have bits 5-6 == 0 (lcb is bit 4 only), so
    // swz(off + kk*32) == swz(off) XOR (kk*32).
    int lrow = (lane & 7) + ((lane >> 3) & 1) * 8;   // 0..15 within 16-row block
    int lcb  = (lane >> 4) * 16;                     // 0 or 16 bytes (k half)
    uint32_t aoff[4], boff[4];
    #pragma unroll
    for (int mi = 0; mi < 4; mi++)
        aoff[mi] = swz((uint32_t)(wm * 64 + mi * 16 + lrow) * 128 + lcb);
    #pragma unroll
    for (int gg = 0; gg < 4; gg++)
        boff[gg] = swz((uint32_t)(wn * 64 + gg * 16 + lrow) * 128 + lcb);

    float acc[4][4][2][4];    // [mi][gg][sub][4] = 128 f32
    #pragma unroll
    for (int i = 0; i < 4; i++)
        #pragma unroll
        for (int j = 0; j < 4; j++)
            #pragma unroll
            for (int k = 0; k < 2; k++)
                #pragma unroll
                for (int l = 0; l < 4; l++) acc[i][j][k][l] = 0.f;

    uint32_t afr[2][4][4], bfr[2][4][4];   // double-buffered fragments

    int s = 0, ph = 0;   // explicit (stage, phase) cursor: NS == 3
    for (int it = 0; it < KITERS; ++it) {
        MBAR_WAIT(sb + SM_FULL + s * 8, ph);

        uint32_t abase = sb + SM_A + s * A_TILE_BYTES;
        uint32_t bbase = sb + SM_B + s * B_TILE_BYTES;

        // prime kk=0 fragments into buffer 0
        #pragma unroll
        for (int mi = 0; mi < 4; mi++)
            ldmx4(afr[0][mi][0], afr[0][mi][1], afr[0][mi][2], afr[0][mi][3],
                  abase + aoff[mi]);
        #pragma unroll
        for (int gg = 0; gg < 4; gg++)
            ldmx4(bfr[0][gg][0], bfr[0][gg][1], bfr[0][gg][2], bfr[0][gg][3],
                  bbase + boff[gg]);

        #pragma unroll
        for (int kk = 0; kk < 4; kk++) {
            int cur = kk & 1, nxt = cur ^ 1;
            if (kk < 3) {                       // prefetch kk+1 while kk's MMAs drain
                uint32_t kx = (uint32_t)((kk + 1) << 5);
                #pragma unroll
                for (int mi = 0; mi < 4; mi++)
                    ldmx4(afr[nxt][mi][0], afr[nxt][mi][1], afr[nxt][mi][2], afr[nxt][mi][3],
                          abase + (aoff[mi] ^ kx));
                #pragma unroll
                for (int gg = 0; gg < 4; gg++)
                    ldmx4(bfr[nxt][gg][0], bfr[nxt][gg][1], bfr[nxt][gg][2], bfr[nxt][gg][3],
                          bbase + (boff[gg] ^ kx));
            }
            #pragma unroll
            for (int mi = 0; mi < 4; mi++)
                #pragma unroll
                for (int gg = 0; gg < 4; gg++) {
                    mma16816(acc[mi][gg][0], afr[cur][mi], bfr[cur][gg][0], bfr[cur][gg][2]);
                    mma16816(acc[mi][gg][1], afr[cur][mi], bfr[cur][gg][1], bfr[cur][gg][3]);
                }
        }

        if (elect_one()) MBAR_ARRIVE(sb + SM_EMPTY + s * 8);

        // refill this slot for iteration it+NS (same parity as our arrive above)
        if (tid == 0 && it + NS < KITERS) {
            MBAR_WAIT(sb + SM_EMPTY + s * 8, ph);
            int nx = it + NS;
            MBAR_EXPECT_TX(sb + SM_FULL + s * 8, A_TILE_BYTES + B_TILE_BYTES);
            bulk_g2s(sb + SM_A + s * A_TILE_BYTES, asrc + (size_t)nx * A_TILE_BYTES,
                     A_TILE_BYTES, sb + SM_FULL + s * 8);
            bulk_g2s(sb + SM_B + s * B_TILE_BYTES, bsrc + (size_t)nx * B_TILE_BYTES,
                     B_TILE_BYTES, sb + SM_FULL + s * 8);
        }
        if (++s == NS) { s = 0; ph ^= 1; }
    }

    // ---- epilogue ----
    float scl = *scale_p;
    const float* bs = (const float*)(smem + SM_BIAS);
    int qrow = lane >> 2;          // 0..7
    int qcol = (lane & 3) * 2;     // 0,2,4,6
    #pragma unroll
    for (int mi = 0; mi < 4; mi++) {
        #pragma unroll
        for (int gg = 0; gg < 4; gg++) {
            #pragma unroll
            for (int sub = 0; sub < 2; sub++) {
                int ncol = wn * 64 + gg * 16 + sub * 8 + qcol;       // local in BN
                int m0   = mt * BM + wm * 64 + mi * 16 + qrow;
                size_t og = (size_t)m0 * D_N + (size_t)nt * BN + ncol;
                float b0 = bs[ncol], b1 = bs[ncol + 1];
                float2 v0, v1;
                v0.x = fmaf(scl, acc[mi][gg][sub][0], b0);
                v0.y = fmaf(scl, acc[mi][gg][sub][1], b1);
                v1.x = fmaf(scl, acc[mi][gg][sub][2], b0);
                v1.y = fmaf(scl, acc[mi][gg][sub][3], b1);
                *(float2*)(out + og) = v0;
                *(float2*)(out + og + (size_t)8 * D_N) = v1;
            }
        }
    }
}

// ---------------- launch ----------------
extern "C" void kernel_launch(void* const* d_in, const int* in_sizes, int n_in,
                              void* d_out, int out_size) {
    const float* x     = (const float*)d_in[0];
    const int*   qw    = (const int*)d_in[1];
    const float* scale = (const float*)d_in[2];
    const float* zp    = (const float*)d_in[3];
    const float* bias  = (const float*)d_in[4];
    float* out = (float*)d_out;

    __half* xt; cudaGetSymbolAddress((void**)&xt, g_xt);
    __half* wt; cudaGetSymbolAddress((void**)&wt, g_wt);

    cudaFuncSetAttribute(gemm_kernel, cudaFuncAttributeMaxDynamicSharedMemorySize, SMEM_TOTAL);

    conv_kernel<<<MT * KITERS + NT * KITERS, 256>>>(x, qw, zp, xt, wt);
    gemm_kernel<<<MT * NT, NTHREADS, SMEM_TOTAL>>>(scale, bias, out);
}

// round 9
// speedup vs baseline: 1.0867x; 1.0589x over previous
#include <cuda_runtime.h>
#include <cuda_fp16.h>
#include <cstdint>

// ---------------- problem constants ----------------
#define D_M   8192      // B*S
#define D_K   4096
#define D_N   11008

#define BM    64
#define BN    128
#define BK    64        // 64 fp16 = 128B rows (SW128 atom)
#define KITERS (D_K / BK)   // 64
#define NS    3             // pipeline stages (explicit cursor)

static constexpr int MT = D_M / BM;   // 128
static constexpr int NT = D_N / BN;   // 86

static constexpr int A_TILE_BYTES = BM * BK * 2;  // 8192
static constexpr int B_TILE_BYTES = BN * BK * 2;  // 16384

static constexpr int NTHREADS = 128;  // 4 warps: 2(M) x 2(N), warp tile 32x64

// smem layout (per CTA ~73 KB -> 3 CTAs/SM)
static constexpr int SM_FULL  = 0;                    // NS * 8
static constexpr int SM_EMPTY = SM_FULL + NS * 8;     // 24
static constexpr int SM_BIAS  = 128;                  // BN floats = 512B
static constexpr int SM_A     = 1024;                              // 1024-aligned
static constexpr int SM_B     = SM_A + NS * A_TILE_BYTES;          // 25600
static constexpr int SMEM_TOTAL = SM_B + NS * B_TILE_BYTES;        // 74752

// ---------------- scratch (tiled, pre-swizzled fp16) ----------------
__device__ __align__(1024) __half g_xt[(size_t)D_M * D_K];   // 64 MiB
__device__ __align__(1024) __half g_wt[(size_t)D_N * D_K];   // 86 MiB

// ---------------- PTX helpers ----------------
__device__ __forceinline__ uint32_t smem_u32(const void* p) {
    uint32_t a;
    asm("{ .reg .u64 t; cvta.to.shared.u64 t, %1; cvt.u32.u64 %0, t; }" : "=r"(a) : "l"(p));
    return a;
}
__device__ __forceinline__ uint32_t elect_one() {
    uint32_t p;
    asm volatile("{ .reg .pred p; elect.sync _|p, 0xFFFFFFFF; selp.b32 %0, 1, 0, p; }" : "=r"(p));
    return p;
}
#define MBAR_INIT(a, cnt) \
    asm volatile("mbarrier.init.shared.b64 [%0], %1;" :: "r"(a), "r"((uint32_t)(cnt)) : "memory")
#define MBAR_EXPECT_TX(a, b) \
    asm volatile("mbarrier.arrive.expect_tx.shared.b64 _, [%0], %1;" :: "r"(a), "r"((uint32_t)(b)) : "memory")
#define MBAR_ARRIVE(a) \
    asm volatile("mbarrier.arrive.shared.b64 _, [%0];" :: "r"(a) : "memory")

#define MBAR_WAIT(a, ph) do {                                                   \
    uint32_t _m = (a); uint32_t _p = (uint32_t)(ph); uint32_t _d;               \
    asm volatile("{ .reg .pred p; mbarrier.try_wait.parity.acquire.cta.shared::cta.b64 p, [%1], %2; selp.b32 %0,1,0,p; }" \
        : "=r"(_d) : "r"(_m), "r"(_p) : "memory");                              \
    if (!_d) { asm volatile("{ .reg .pred P1; WL%=:\n\t"                        \
        "mbarrier.try_wait.parity.acquire.cta.shared::cta.b64 P1, [%0], %1, 0x989680;\n\t" \
        "@P1 bra.uni WD%=;\n\t bra.uni WL%=;\n\t WD%=: }"                       \
        :: "r"(_m), "r"(_p) : "memory"); }                                      \
} while (0)

__device__ __forceinline__ void bulk_g2s(uint32_t dst, const void* src, uint32_t bytes, uint32_t mbar) {
    asm volatile("cp.async.bulk.shared::cta.global.mbarrier::complete_tx::bytes [%0], [%1], %2, [%3];"
        :: "r"(dst), "l"(src), "r"(bytes), "r"(mbar) : "memory");
}

__device__ __forceinline__ void ldmx4(uint32_t& r0, uint32_t& r1, uint32_t& r2, uint32_t& r3, uint32_t a) {
    asm volatile("ldmatrix.sync.aligned.m8n8.x4.shared.b16 {%0,%1,%2,%3}, [%4];"
        : "=r"(r0), "=r"(r1), "=r"(r2), "=r"(r3) : "r"(a));
}

__device__ __forceinline__ void mma16816(float* c, const uint32_t* a, uint32_t b0, uint32_t b1) {
    asm volatile("mma.sync.aligned.m16n8k16.row.col.f32.f16.f16.f32 "
        "{%0,%1,%2,%3}, {%4,%5,%6,%7}, {%8,%9}, {%0,%1,%2,%3};"
        : "+f"(c[0]), "+f"(c[1]), "+f"(c[2]), "+f"(c[3])
        : "r"(a[0]), "r"(a[1]), "r"(a[2]), "r"(a[3]), "r"(b0), "r"(b1));
}

__device__ __forceinline__ uint32_t swz(uint32_t off) { return off ^ ((off >> 3) & 0x70); }

// ---------------- fused converter kernel (pre-swizzled fp16 tiles) ----------------
__global__ void conv_kernel(const float* __restrict__ x, const int* __restrict__ qw,
                            const float* __restrict__ zp_p,
                            __half* __restrict__ xt, __half* __restrict__ wt) {
    int b = blockIdx.x;
    if (b < MT * KITERS) {
        int mt = b / KITERS, kc = b % KITERS;
        const float* src = x + (size_t)mt * BM * D_K + (size_t)kc * BK;
        char* dst = (char*)(xt + (size_t)b * (BM * BK));
        for (int i = threadIdx.x; i < BM * BK / 2; i += blockDim.x) {
            int row = i >> 5, c2 = i & 31;
            float2 v = *(const float2*)(src + (size_t)row * D_K + c2 * 2);
            __half2 h = __floats2half2_rn(v.x, v.y);
            *(__half2*)(dst + swz(row * 128 + c2 * 4)) = h;
        }
    } else {
        int t = b - MT * KITERS;
        float zp = *zp_p;
        int nt = t / KITERS, kc = t % KITERS;
        const int* src = qw + (size_t)nt * BN * D_K + (size_t)kc * BK;
        char* dst = (char*)(wt + (size_t)t * (BN * BK));
        for (int i = threadIdx.x; i < BN * BK / 2; i += blockDim.x) {
            int row = i >> 5, c2 = i & 31;
            int2 q = *(const int2*)(src + (size_t)row * D_K + c2 * 2);
            __half2 h = __floats2half2_rn((float)q.x - zp, (float)q.y - zp);
            *(__half2*)(dst + swz(row * 128 + c2 * 4)) = h;
        }
    }
}

// ---------------- main GEMM kernel ----------------
// 128 threads, 4 warps in 2(M) x 2(N); warp tile 32 x 64. 3 CTAs / SM
// (reg cap 170 -> room for double-buffered fragments: LDSM prefetch of kk+1
//  issued before kk's MMA block, hiding the LDSM->MMA scoreboard stall).
// Barrier discipline is R5's proven one: empty-arrive strictly AFTER all MMAs.
__global__ void __launch_bounds__(NTHREADS, 3)
gemm_kernel(const float* __restrict__ scale_p, const float* __restrict__ bias,
            float* __restrict__ out) {
    extern __shared__ char smem[];
    uint32_t sb = smem_u32(smem);
    int tid = threadIdx.x, wid = tid >> 5, lane = tid & 31;
    int wm = wid & 1;          // 0..1  (M)
    int wn = wid >> 1;         // 0..1  (N)

    // tile decode with M-group swizzle for L2 reuse
    const int GROUP = 16;
    int bid = blockIdx.x;
    int tpg = GROUP * NT;
    int g = bid / tpg, r = bid % tpg;
    int mt = g * GROUP + (r % GROUP);
    int nt = r / GROUP;

    if (tid == 0) {
        for (int s = 0; s < NS; s++) {
            MBAR_INIT(sb + SM_FULL  + s * 8, 1);
            MBAR_INIT(sb + SM_EMPTY + s * 8, 4);
        }
    }
    for (int i = tid; i < BN; i += NTHREADS)
        ((float*)(smem + SM_BIAS))[i] = bias[(size_t)nt * BN + i];
    __syncthreads();

    const char* asrc = (const char*)g_xt + (size_t)mt * KITERS * A_TILE_BYTES;
    const char* bsrc = (const char*)g_wt + (size_t)nt * KITERS * B_TILE_BYTES;

    // prologue: fill all NS stages
    if (tid == 0) {
        for (int s = 0; s < NS; s++) {
            MBAR_EXPECT_TX(sb + SM_FULL + s * 8, A_TILE_BYTES + B_TILE_BYTES);
            bulk_g2s(sb + SM_A + s * A_TILE_BYTES, asrc + (size_t)s * A_TILE_BYTES,
                     A_TILE_BYTES, sb + SM_FULL + s * 8);
            bulk_g2s(sb + SM_B + s * B_TILE_BYTES, bsrc + (size_t)s * B_TILE_BYTES,
                     B_TILE_BYTES, sb + SM_FULL + s * 8);
        }
    }

    // per-lane ldmatrix addressing: hoisted swizzled bases.
    // Pre-swizzle offsets have bits 5-6 == 0 (lcb is bit 4 only), so
    // swz(off + kk*32) == swz(off) XOR (kk*32).
    int lrow = (lane & 7) + ((lane >> 3) & 1) * 8;   // 0..15 within 16-row block
    int lcb  = (lane >> 4) * 16;                     // 0 or 16 bytes (k half)
    uint32_t aoff[2], boff[4];
    #pragma unroll
    for (int mi = 0; mi < 2; mi++)
        aoff[mi] = swz((uint32_t)(wm * 32 + mi * 16 + lrow) * 128 + lcb);
    #pragma unroll
    for (int gg = 0; gg < 4; gg++)
        boff[gg] = swz((uint32_t)(wn * 64 + gg * 16 + lrow) * 128 + lcb);

    float acc[2][4][2][4];    // [mi][gg][sub][4] = 64 f32
    #pragma unroll
    for (int i = 0; i < 2; i++)
        #pragma unroll
        for (int j = 0; j < 4; j++)
            #pragma unroll
            for (int k = 0; k < 2; k++)
                #pragma unroll
                for (int l = 0; l < 4; l++) acc[i][j][k][l] = 0.f;

    uint32_t afr[2][2][4], bfr[2][4][4];   // double-buffered fragments

    int s = 0, ph = 0;   // explicit (stage, phase) cursor: NS == 3
    for (int it = 0; it < KITERS; ++it) {
        MBAR_WAIT(sb + SM_FULL + s * 8, ph);

        uint32_t abase = sb + SM_A + s * A_TILE_BYTES;
        uint32_t bbase = sb + SM_B + s * B_TILE_BYTES;

        // prime kk=0 fragments into buffer 0
        #pragma unroll
        for (int mi = 0; mi < 2; mi++)
            ldmx4(afr[0][mi][0], afr[0][mi][1], afr[0][mi][2], afr[0][mi][3],
                  abase + aoff[mi]);
        #pragma unroll
        for (int gg = 0; gg < 4; gg++)
            ldmx4(bfr[0][gg][0], bfr[0][gg][1], bfr[0][gg][2], bfr[0][gg][3],
                  bbase + boff[gg]);

        #pragma unroll
        for (int kk = 0; kk < 4; kk++) {
            int cur = kk & 1, nxt = cur ^ 1;
            if (kk < 3) {                       // prefetch kk+1 while kk's MMAs drain
                uint32_t kx = (uint32_t)((kk + 1) << 5);
                #pragma unroll
                for (int mi = 0; mi < 2; mi++)
                    ldmx4(afr[nxt][mi][0], afr[nxt][mi][1], afr[nxt][mi][2], afr[nxt][mi][3],
                          abase + (aoff[mi] ^ kx));
                #pragma unroll
                for (int gg = 0; gg < 4; gg++)
                    ldmx4(bfr[nxt][gg][0], bfr[nxt][gg][1], bfr[nxt][gg][2], bfr[nxt][gg][3],
                          bbase + (boff[gg] ^ kx));
            }
            #pragma unroll
            for (int mi = 0; mi < 2; mi++)
                #pragma unroll
                for (int gg = 0; gg < 4; gg++) {
                    mma16816(acc[mi][gg][0], afr[cur][mi], bfr[cur][gg][0], bfr[cur][gg][2]);
                    mma16816(acc[mi][gg][1], afr[cur][mi], bfr[cur][gg][1], bfr[cur][gg][3]);
                }
        }

        // release the slot only after ALL MMAs of this stage (R5-proven safe order)
        if (elect_one()) MBAR_ARRIVE(sb + SM_EMPTY + s * 8);

        if (tid == 0 && it + NS < KITERS) {
            MBAR_WAIT(sb + SM_EMPTY + s * 8, ph);
            int nx = it + NS;
            MBAR_EXPECT_TX(sb + SM_FULL + s * 8, A_TILE_BYTES + B_TILE_BYTES);
            bulk_g2s(sb + SM_A + s * A_TILE_BYTES, asrc + (size_t)nx * A_TILE_BYTES,
                     A_TILE_BYTES, sb + SM_FULL + s * 8);
            bulk_g2s(sb + SM_B + s * B_TILE_BYTES, bsrc + (size_t)nx * B_TILE_BYTES,
                     B_TILE_BYTES, sb + SM_FULL + s * 8);
        }
        if (++s == NS) { s = 0; ph ^= 1; }
    }

    // ---- epilogue ----
    float scl = *scale_p;
    const float* bs = (const float*)(smem + SM_BIAS);
    int qrow = lane >> 2;          // 0..7
    int qcol = (lane & 3) * 2;     // 0,2,4,6
    #pragma unroll
    for (int mi = 0; mi < 2; mi++) {
        #pragma unroll
        for (int gg = 0; gg < 4; gg++) {
            #pragma unroll
            for (int sub = 0; sub < 2; sub++) {
                int ncol = wn * 64 + gg * 16 + sub * 8 + qcol;       // local in BN
                int m0   = mt * BM + wm * 32 + mi * 16 + qrow;
                size_t og = (size_t)m0 * D_N + (size_t)nt * BN + ncol;
                float b0 = bs[ncol], b1 = bs[ncol + 1];
                float2 v0, v1;
                v0.x = fmaf(scl, acc[mi][gg][sub][0], b0);
                v0.y = fmaf(scl, acc[mi][gg][sub][1], b1);
                v1.x = fmaf(scl, acc[mi][gg][sub][2], b0);
                v1.y = fmaf(scl, acc[mi][gg][sub][3], b1);
                *(float2*)(out + og) = v0;
                *(float2*)(out + og + (size_t)8 * D_N) = v1;
            }
        }
    }
}

// ---------------- launch ----------------
extern "C" void kernel_launch(void* const* d_in, const int* in_sizes, int n_in,
                              void* d_out, int out_size) {
    const float* x     = (const float*)d_in[0];
    const int*   qw    = (const int*)d_in[1];
    const float* scale = (const float*)d_in[2];
    const float* zp    = (const float*)d_in[3];
    const float* bias  = (const float*)d_in[4];
    float* out = (float*)d_out;

    __half* xt; cudaGetSymbolAddress((void**)&xt, g_xt);
    __half* wt; cudaGetSymbolAddress((void**)&wt, g_wt);

    cudaFuncSetAttribute(gemm_kernel, cudaFuncAttributeMaxDynamicSharedMemorySize, SMEM_TOTAL);

    conv_kernel<<<MT * KITERS + NT * KITERS, 256>>>(x, qw, zp, xt, wt);
    gemm_kernel<<<MT * NT, NTHREADS, SMEM_TOTAL>>>(scale, bias, out);
}

// round 10
// speedup vs baseline: 1.2099x; 1.1134x over previous
#include <cuda_runtime.h>
#include <cuda_fp16.h>
#include <cstdint>

// ---------------- problem constants ----------------
#define D_M   8192      // B*S
#define D_K   4096
#define D_N   11008

#define BM    64
#define BN    128
#define BK    64        // 64 fp16 = 128B rows (SW128 atom)
#define KITERS (D_K / BK)   // 64
#define NS    3             // pipeline stages (explicit cursor)

static constexpr int MT = D_M / BM;   // 128
static constexpr int NT = D_N / BN;   // 86

static constexpr int A_TILE_BYTES = BM * BK * 2;  // 8192
static constexpr int B_TILE_BYTES = BN * BK * 2;  // 16384

static constexpr int NTHREADS = 128;  // 4 warps: 2(M) x 2(N), warp tile 32x64

// smem layout (per CTA ~73 KB -> 3 CTAs/SM)
static constexpr int SM_FULL  = 0;                    // NS * 8
static constexpr int SM_EMPTY = SM_FULL + NS * 8;     // 24
static constexpr int SM_BIAS  = 128;                  // BN floats = 512B
static constexpr int SM_A     = 1024;                              // 1024-aligned
static constexpr int SM_B     = SM_A + NS * A_TILE_BYTES;          // 25600
static constexpr int SMEM_TOTAL = SM_B + NS * B_TILE_BYTES;        // 74752

// ---------------- scratch (tiled, pre-swizzled fp16) ----------------
__device__ __align__(1024) __half g_xt[(size_t)D_M * D_K];   // 64 MiB
__device__ __align__(1024) __half g_wt[(size_t)D_N * D_K];   // 86 MiB

// ---------------- PTX helpers ----------------
__device__ __forceinline__ uint32_t smem_u32(const void* p) {
    uint32_t a;
    asm("{ .reg .u64 t; cvta.to.shared.u64 t, %1; cvt.u32.u64 %0, t; }" : "=r"(a) : "l"(p));
    return a;
}
__device__ __forceinline__ uint32_t elect_one() {
    uint32_t p;
    asm volatile("{ .reg .pred p; elect.sync _|p, 0xFFFFFFFF; selp.b32 %0, 1, 0, p; }" : "=r"(p));
    return p;
}
#define MBAR_INIT(a, cnt) \
    asm volatile("mbarrier.init.shared.b64 [%0], %1;" :: "r"(a), "r"((uint32_t)(cnt)) : "memory")
#define MBAR_EXPECT_TX(a, b) \
    asm volatile("mbarrier.arrive.expect_tx.shared.b64 _, [%0], %1;" :: "r"(a), "r"((uint32_t)(b)) : "memory")
#define MBAR_ARRIVE(a) \
    asm volatile("mbarrier.arrive.shared.b64 _, [%0];" :: "r"(a) : "memory")

#define MBAR_WAIT(a, ph) do {                                                   \
    uint32_t _m = (a); uint32_t _p = (uint32_t)(ph); uint32_t _d;               \
    asm volatile("{ .reg .pred p; mbarrier.try_wait.parity.acquire.cta.shared::cta.b64 p, [%1], %2; selp.b32 %0,1,0,p; }" \
        : "=r"(_d) : "r"(_m), "r"(_p) : "memory");                              \
    if (!_d) { asm volatile("{ .reg .pred P1; WL%=:\n\t"                        \
        "mbarrier.try_wait.parity.acquire.cta.shared::cta.b64 P1, [%0], %1, 0x989680;\n\t" \
        "@P1 bra.uni WD%=;\n\t bra.uni WL%=;\n\t WD%=: }"                       \
        :: "r"(_m), "r"(_p) : "memory"); }                                      \
} while (0)

__device__ __forceinline__ void bulk_g2s(uint32_t dst, const void* src, uint32_t bytes, uint32_t mbar) {
    asm volatile("cp.async.bulk.shared::cta.global.mbarrier::complete_tx::bytes [%0], [%1], %2, [%3];"
        :: "r"(dst), "l"(src), "r"(bytes), "r"(mbar) : "memory");
}

__device__ __forceinline__ void ldmx4(uint32_t& r0, uint32_t& r1, uint32_t& r2, uint32_t& r3, uint32_t a) {
    asm volatile("ldmatrix.sync.aligned.m8n8.x4.shared.b16 {%0,%1,%2,%3}, [%4];"
        : "=r"(r0), "=r"(r1), "=r"(r2), "=r"(r3) : "r"(a));
}

__device__ __forceinline__ void mma16816(float* c, const uint32_t* a, uint32_t b0, uint32_t b1) {
    asm volatile("mma.sync.aligned.m16n8k16.row.col.f32.f16.f16.f32 "
        "{%0,%1,%2,%3}, {%4,%5,%6,%7}, {%8,%9}, {%0,%1,%2,%3};"
        : "+f"(c[0]), "+f"(c[1]), "+f"(c[2]), "+f"(c[3])
        : "r"(a[0]), "r"(a[1]), "r"(a[2]), "r"(a[3]), "r"(b0), "r"(b1));
}

__device__ __forceinline__ uint32_t swz(uint32_t off) { return off ^ ((off >> 3) & 0x70); }

// ---------------- fused converter kernel (pre-swizzled fp16 tiles) ----------------
__global__ void conv_kernel(const float* __restrict__ x, const int* __restrict__ qw,
                            const float* __restrict__ zp_p,
                            __half* __restrict__ xt, __half* __restrict__ wt) {
    int b = blockIdx.x;
    if (b < MT * KITERS) {
        int mt = b / KITERS, kc = b % KITERS;
        const float* src = x + (size_t)mt * BM * D_K + (size_t)kc * BK;
        char* dst = (char*)(xt + (size_t)b * (BM * BK));
        for (int i = threadIdx.x; i < BM * BK / 2; i += blockDim.x) {
            int row = i >> 5, c2 = i & 31;
            float2 v = *(const float2*)(src + (size_t)row * D_K + c2 * 2);
            __half2 h = __floats2half2_rn(v.x, v.y);
            *(__half2*)(dst + swz(row * 128 + c2 * 4)) = h;
        }
    } else {
        int t = b - MT * KITERS;
        float zp = *zp_p;
        int nt = t / KITERS, kc = t % KITERS;
        const int* src = qw + (size_t)nt * BN * D_K + (size_t)kc * BK;
        char* dst = (char*)(wt + (size_t)t * (BN * BK));
        for (int i = threadIdx.x; i < BN * BK / 2; i += blockDim.x) {
            int row = i >> 5, c2 = i & 31;
            int2 q = *(const int2*)(src + (size_t)row * D_K + c2 * 2);
            __half2 h = __floats2half2_rn((float)q.x - zp, (float)q.y - zp);
            *(__half2*)(dst + swz(row * 128 + c2 * 4)) = h;
        }
    }
}

// ---------------- main GEMM kernel ----------------
// 128 threads, 4 warps in 2(M) x 2(N); warp tile 32 x 64. 3 CTAs / SM.
// Cross-stage fragment prefetch (CUTLASS multistage style): at kk==3 the warp
// waits full(s+1) and LDSM-prefetches stage s+1's kk0 fragments BEFORE the
// final MMA block, so the TRYWAIT + LDSM latency drain under MMAs. The
// empty-arrive for stage s remains strictly AFTER all of its MMAs.
__global__ void __launch_bounds__(NTHREADS, 3)
gemm_kernel(const float* __restrict__ scale_p, const float* __restrict__ bias,
            float* __restrict__ out) {
    extern __shared__ char smem[];
    uint32_t sb = smem_u32(smem);
    int tid = threadIdx.x, wid = tid >> 5, lane = tid & 31;
    int wm = wid & 1;          // 0..1  (M)
    int wn = wid >> 1;         // 0..1  (N)

    // tile decode with M-group swizzle for L2 reuse
    const int GROUP = 16;
    int bid = blockIdx.x;
    int tpg = GROUP * NT;
    int g = bid / tpg, r = bid % tpg;
    int mt = g * GROUP + (r % GROUP);
    int nt = r / GROUP;

    if (tid == 0) {
        for (int s = 0; s < NS; s++) {
            MBAR_INIT(sb + SM_FULL  + s * 8, 1);
            MBAR_INIT(sb + SM_EMPTY + s * 8, 4);
        }
    }
    for (int i = tid; i < BN; i += NTHREADS)
        ((float*)(smem + SM_BIAS))[i] = bias[(size_t)nt * BN + i];
    __syncthreads();

    const char* asrc = (const char*)g_xt + (size_t)mt * KITERS * A_TILE_BYTES;
    const char* bsrc = (const char*)g_wt + (size_t)nt * KITERS * B_TILE_BYTES;

    // prologue: fill all NS stages
    if (tid == 0) {
        for (int s = 0; s < NS; s++) {
            MBAR_EXPECT_TX(sb + SM_FULL + s * 8, A_TILE_BYTES + B_TILE_BYTES);
            bulk_g2s(sb + SM_A + s * A_TILE_BYTES, asrc + (size_t)s * A_TILE_BYTES,
                     A_TILE_BYTES, sb + SM_FULL + s * 8);
            bulk_g2s(sb + SM_B + s * B_TILE_BYTES, bsrc + (size_t)s * B_TILE_BYTES,
                     B_TILE_BYTES, sb + SM_FULL + s * 8);
        }
    }

    // per-lane ldmatrix addressing: hoisted swizzled bases.
    // Pre-swizzle offsets have bits 5-6 == 0 (lcb is bit 4 only), so
    // swz(off + kk*32) == swz(off) XOR (kk*32).
    int lrow = (lane & 7) + ((lane >> 3) & 1) * 8;   // 0..15 within 16-row block
    int lcb  = (lane >> 4) * 16;                     // 0 or 16 bytes (k half)
    uint32_t aoff[2], boff[4];
    #pragma unroll
    for (int mi = 0; mi < 2; mi++)
        aoff[mi] = swz((uint32_t)(wm * 32 + mi * 16 + lrow) * 128 + lcb);
    #pragma unroll
    for (int gg = 0; gg < 4; gg++)
        boff[gg] = swz((uint32_t)(wn * 64 + gg * 16 + lrow) * 128 + lcb);

    float acc[2][4][2][4];    // [mi][gg][sub][4] = 64 f32
    #pragma unroll
    for (int i = 0; i < 2; i++)
        #pragma unroll
        for (int j = 0; j < 4; j++)
            #pragma unroll
            for (int k = 0; k < 2; k++)
                #pragma unroll
                for (int l = 0; l < 4; l++) acc[i][j][k][l] = 0.f;

    uint32_t afr[2][2][4], bfr[2][4][4];   // double-buffered fragments

    // ---- prologue prime: wait stage 0, load its kk0 fragments into buf 0 ----
    MBAR_WAIT(sb + SM_FULL + 0 * 8, 0);
    {
        uint32_t abase = sb + SM_A, bbase = sb + SM_B;
        #pragma unroll
        for (int mi = 0; mi < 2; mi++)
            ldmx4(afr[0][mi][0], afr[0][mi][1], afr[0][mi][2], afr[0][mi][3],
                  abase + aoff[mi]);
        #pragma unroll
        for (int gg = 0; gg < 4; gg++)
            ldmx4(bfr[0][gg][0], bfr[0][gg][1], bfr[0][gg][2], bfr[0][gg][3],
                  bbase + boff[gg]);
    }

    int s = 0, ph = 0;   // explicit (stage, phase) cursor: NS == 3
    for (int it = 0; it < KITERS; ++it) {
        uint32_t abase = sb + SM_A + s * A_TILE_BYTES;
        uint32_t bbase = sb + SM_B + s * B_TILE_BYTES;
        int sn  = (s + 1 == NS) ? 0 : s + 1;          // next stage slot
        int phn = (s + 1 == NS) ? (ph ^ 1) : ph;      // next stage phase

        #pragma unroll
        for (int kk = 0; kk < 4; kk++) {
            int cur = kk & 1, nxt = cur ^ 1;
            if (kk < 3) {                   // prefetch kk+1 of current stage
                uint32_t kx = (uint32_t)((kk + 1) << 5);
                #pragma unroll
                for (int mi = 0; mi < 2; mi++)
                    ldmx4(afr[nxt][mi][0], afr[nxt][mi][1], afr[nxt][mi][2], afr[nxt][mi][3],
                          abase + (aoff[mi] ^ kx));
                #pragma unroll
                for (int gg = 0; gg < 4; gg++)
                    ldmx4(bfr[nxt][gg][0], bfr[nxt][gg][1], bfr[nxt][gg][2], bfr[nxt][gg][3],
                          bbase + (boff[gg] ^ kx));
            } else if (it + 1 < KITERS) {
                // cross-stage prefetch: wait next stage full, load its kk0
                // fragments (into buf0) BEFORE this stage's final MMA block.
                MBAR_WAIT(sb + SM_FULL + sn * 8, phn);
                uint32_t abn = sb + SM_A + sn * A_TILE_BYTES;
                uint32_t bbn = sb + SM_B + sn * B_TILE_BYTES;
                #pragma unroll
                for (int mi = 0; mi < 2; mi++)
                    ldmx4(afr[nxt][mi][0], afr[nxt][mi][1], afr[nxt][mi][2], afr[nxt][mi][3],
                          abn + aoff[mi]);
                #pragma unroll
                for (int gg = 0; gg < 4; gg++)
                    ldmx4(bfr[nxt][gg][0], bfr[nxt][gg][1], bfr[nxt][gg][2], bfr[nxt][gg][3],
                          bbn + boff[gg]);
            }
            #pragma unroll
            for (int mi = 0; mi < 2; mi++)
                #pragma unroll
                for (int gg = 0; gg < 4; gg++) {
                    mma16816(acc[mi][gg][0], afr[cur][mi], bfr[cur][gg][0], bfr[cur][gg][2]);
                    mma16816(acc[mi][gg][1], afr[cur][mi], bfr[cur][gg][1], bfr[cur][gg][3]);
                }
        }

        // release the slot only after ALL MMAs of this stage
        if (elect_one()) MBAR_ARRIVE(sb + SM_EMPTY + s * 8);

        if (tid == 0 && it + NS < KITERS) {
            MBAR_WAIT(sb + SM_EMPTY + s * 8, ph);
            int nx = it + NS;
            MBAR_EXPECT_TX(sb + SM_FULL + s * 8, A_TILE_BYTES + B_TILE_BYTES);
            bulk_g2s(sb + SM_A + s * A_TILE_BYTES, asrc + (size_t)nx * A_TILE_BYTES,
                     A_TILE_BYTES, sb + SM_FULL + s * 8);
            bulk_g2s(sb + SM_B + s * B_TILE_BYTES, bsrc + (size_t)nx * B_TILE_BYTES,
                     B_TILE_BYTES, sb + SM_FULL + s * 8);
        }
        s = sn; ph = phn;
    }

    // ---- epilogue ----
    float scl = *scale_p;
    const float* bs = (const float*)(smem + SM_BIAS);
    int qrow = lane >> 2;          // 0..7
    int qcol = (lane & 3) * 2;     // 0,2,4,6
    #pragma unroll
    for (int mi = 0; mi < 2; mi++) {
        #pragma unroll
        for (int gg = 0; gg < 4; gg++) {
            #pragma unroll
            for (int sub = 0; sub < 2; sub++) {
                int ncol = wn * 64 + gg * 16 + sub * 8 + qcol;       // local in BN
                int m0   = mt * BM + wm * 32 + mi * 16 + qrow;
                size_t og = (size_t)m0 * D_N + (size_t)nt * BN + ncol;
                float b0 = bs[ncol], b1 = bs[ncol + 1];
                float2 v0, v1;
                v0.x = fmaf(scl, acc[mi][gg][sub][0], b0);
                v0.y = fmaf(scl, acc[mi][gg][sub][1], b1);
                v1.x = fmaf(scl, acc[mi][gg][sub][2], b0);
                v1.y = fmaf(scl, acc[mi][gg][sub][3], b1);
                *(float2*)(out + og) = v0;
                *(float2*)(out + og + (size_t)8 * D_N) = v1;
            }
        }
    }
}

// ---------------- launch ----------------
extern "C" void kernel_launch(void* const* d_in, const int* in_sizes, int n_in,
                              void* d_out, int out_size) {
    const float* x     = (const float*)d_in[0];
    const int*   qw    = (const int*)d_in[1];
    const float* scale = (const float*)d_in[2];
    const float* zp    = (const float*)d_in[3];
    const float* bias  = (const float*)d_in[4];
    float* out = (float*)d_out;

    __half* xt; cudaGetSymbolAddress((void**)&xt, g_xt);
    __half* wt; cudaGetSymbolAddress((void**)&wt, g_wt);

    cudaFuncSetAttribute(gemm_kernel, cudaFuncAttributeMaxDynamicSharedMemorySize, SMEM_TOTAL);

    conv_kernel<<<MT * KITERS + NT * KITERS, 256>>>(x, qw, zp, xt, wt);
    gemm_kernel<<<MT * NT, NTHREADS, SMEM_TOTAL>>>(scale, bias, out);
}